// round 6
// baseline (speedup 1.0000x reference)
#include <cuda_runtime.h>
#include <cuda_bf16.h>

typedef unsigned long long u64;

__device__ __forceinline__ u64 pk2(float lo, float hi) {
    u64 d; asm("mov.b64 %0, {%1, %2};" : "=l"(d) : "f"(lo), "f"(hi)); return d;
}
__device__ __forceinline__ void upk2(u64 v, float& lo, float& hi) {
    asm("mov.b64 {%0, %1}, %2;" : "=f"(lo), "=f"(hi) : "l"(v));
}
__device__ __forceinline__ u64 fma2(u64 a, u64 b, u64 c) {
    u64 d; asm("fma.rn.f32x2 %0, %1, %2, %3;" : "=l"(d) : "l"(a), "l"(b), "l"(c)); return d;
}

__device__ __forceinline__ int q_of(float t) {
    // t*1024 is exact in fp32 (power-of-two scale), so truncation == floor,
    // matching the reference's interval comparisons bit-exactly.
    int q = (int)(t * 1024.0f);
    q = q < 0 ? 0 : (q > 1023 ? 1023 : q);
    return q;
}

// Fused: each block builds the 1024-entry LUT in shared memory (1 sibling
// pair per thread, 512 threads), then applies it (1 float4 per thread).
__global__ void __launch_bounds__(512) haar_fused(const float* __restrict__ t,
                                                  const float* __restrict__ W1,
                                                  const float* __restrict__ b1,
                                                  const float* __restrict__ W2,
                                                  const float* __restrict__ b2,
                                                  const float* __restrict__ W3,
                                                  const float* __restrict__ b3,
                                                  float* __restrict__ out,
                                                  int n) {
    __shared__ float4 tab[1024];
    __shared__ u64 w2s[32];   // w2s[h*4+kk] = (W2[h][2kk], W2[h][2kk+1])
    __shared__ u64 w3s[12];   // w3s[f*4+kk] = (W3[2kk][f], W3[2kk+1][f])
    __shared__ u64 b1s[4];
    __shared__ u64 b2s[4];
    __shared__ float b3s[3];

    int tid = threadIdx.x;
    int i = blockIdx.x * blockDim.x + tid;
    int n4 = n >> 2;

    // ---- Prefetch this thread's input points (latency hides behind build) ----
    const float4* t4 = reinterpret_cast<const float4*>(t);
    float4 tv = make_float4(0.f, 0.f, 0.f, 0.f);
    if (i < n4) tv = t4[i];
    int tail_start = n4 << 2;
    int tail_n = n - tail_start;
    float t_tail = 0.f;
    if (i < tail_n) t_tail = t[tail_start + i];

    // ---- Stage small weights into shared memory (broadcast reads later) ----
    if (tid < 32) {
        w2s[tid] = reinterpret_cast<const u64*>(W2)[tid];  // pairs are contiguous
    } else if (tid < 44) {
        int r = tid - 32;
        int f = r % 3, kk = r / 3;
        w3s[f * 4 + kk] = pk2(W3[(2 * kk) * 3 + f], W3[(2 * kk + 1) * 3 + f]);
    } else if (tid < 48) {
        b1s[tid - 44] = reinterpret_cast<const u64*>(b1)[tid - 44];
    } else if (tid < 52) {
        b2s[tid - 48] = reinterpret_cast<const u64*>(b2)[tid - 48];
    } else if (tid < 55) {
        b3s[tid - 52] = b3[tid - 52];
    }
    __syncthreads();

    const ulonglong2* w1v = reinterpret_cast<const ulonglong2*>(W1);

    // ---- Build: ONE sibling pair (entries 2m, 2m+1) per thread ----
    {
        int m = tid;   // 0..511

        u64 base2[4];
#pragma unroll
        for (int h = 0; h < 4; h++) base2[h] = b1s[h];

        // Levels 0..8 shared by the sibling pair.
#pragma unroll
        for (int j = 0; j < 9; j++) {
            int k   = m >> (9 - j);
            int row = (1 << j) - 1 + k;
            float s = ((m >> (8 - j)) & 1) ? -1.0f : 1.0f;
            u64 s2 = pk2(s, s);
            ulonglong2 r0 = __ldg(w1v + row * 2);
            ulonglong2 r1 = __ldg(w1v + row * 2 + 1);
            base2[0] = fma2(s2, r0.x, base2[0]);
            base2[1] = fma2(s2, r0.y, base2[1]);
            base2[2] = fma2(s2, r1.x, base2[2]);
            base2[3] = fma2(s2, r1.y, base2[3]);
        }

        // Level-9 row for this pair.
        ulonglong2 f0 = __ldg(w1v + (511 + m) * 2);
        ulonglong2 f1 = __ldg(w1v + (511 + m) * 2 + 1);
        u64 fine2[4] = { f0.x, f0.y, f1.x, f1.y };

#pragma unroll
        for (int c = 0; c < 2; c++) {
            float sgn = c ? -1.0f : 1.0f;
            u64 sg2 = pk2(sgn, sgn);

            // acc = base + sgn*fine, ReLU, broadcast each lane into a pair.
            u64 bc[8];
#pragma unroll
            for (int h = 0; h < 4; h++) {
                u64 a2 = fma2(sg2, fine2[h], base2[h]);
                float lo, hi; upk2(a2, lo, hi);
                lo = fmaxf(lo, 0.0f); hi = fmaxf(hi, 0.0f);
                bc[2*h]   = pk2(lo, lo);
                bc[2*h+1] = pk2(hi, hi);
            }

            // Layer 2: h2 pairs (k, k+1); W2 pairs broadcast from smem.
            u64 h2p[4];
#pragma unroll
            for (int kk = 0; kk < 4; kk++) h2p[kk] = b2s[kk];
#pragma unroll
            for (int h = 0; h < 8; h++) {
#pragma unroll
                for (int kk = 0; kk < 4; kk++)
                    h2p[kk] = fma2(bc[h], w2s[h * 4 + kk], h2p[kk]);
            }
#pragma unroll
            for (int kk = 0; kk < 4; kk++) {
                float lo, hi; upk2(h2p[kk], lo, hi);
                h2p[kk] = pk2(fmaxf(lo, 0.0f), fmaxf(hi, 0.0f));
            }

            // Layer 3: packed dot over k-pairs + horizontal add.
            float o[3];
#pragma unroll
            for (int f = 0; f < 3; f++) {
                u64 acc = pk2(b3s[f], 0.0f);
#pragma unroll
                for (int kk = 0; kk < 4; kk++)
                    acc = fma2(h2p[kk], w3s[f * 4 + kk], acc);
                float lo, hi; upk2(acc, lo, hi);
                o[f] = lo + hi;
            }

            tab[2 * m + c] = make_float4(o[0], o[1], o[2], 0.0f);
        }
    }

    __syncthreads();

    // ---- Apply: 4 points (one float4) per thread ----
    float4* o4 = reinterpret_cast<float4*>(out);
    if (i < n4) {
        float4 r0 = tab[q_of(tv.x)];
        float4 r1 = tab[q_of(tv.y)];
        float4 r2 = tab[q_of(tv.z)];
        float4 r3 = tab[q_of(tv.w)];

        o4[3 * i + 0] = make_float4(r0.x, r0.y, r0.z, r1.x);
        o4[3 * i + 1] = make_float4(r1.y, r1.z, r2.x, r2.y);
        o4[3 * i + 2] = make_float4(r2.z, r3.x, r3.y, r3.z);
    }

    // Scalar tail (n not divisible by 4) — dead for n = 131072 but kept correct.
    if (i < tail_n) {
        int pidx = tail_start + i;
        float4 r = tab[q_of(t_tail)];
        out[3 * pidx + 0] = r.x;
        out[3 * pidx + 1] = r.y;
        out[3 * pidx + 2] = r.z;
    }
}

extern "C" void kernel_launch(void* const* d_in, const int* in_sizes, int n_in,
                              void* d_out, int out_size) {
    const float* t  = (const float*)d_in[0];
    const float* W1 = (const float*)d_in[1];
    const float* b1 = (const float*)d_in[2];
    const float* W2 = (const float*)d_in[3];
    const float* b2 = (const float*)d_in[4];
    const float* W3 = (const float*)d_in[5];
    const float* b3 = (const float*)d_in[6];
    float* out = (float*)d_out;

    int n = in_sizes[0];  // B*T points

    int n4 = n >> 2;
    int threads = 512;
    int blocks = (n4 + threads - 1) / threads;
    if (blocks < 1) blocks = 1;
    haar_fused<<<blocks, threads>>>(t, W1, b1, W2, b2, W3, b3, out, n);
}

// round 7
// speedup vs baseline: 1.1472x; 1.1472x over previous
#include <cuda_runtime.h>
#include <cuda_bf16.h>

typedef unsigned long long u64;

__device__ __forceinline__ u64 pk2(float lo, float hi) {
    u64 d; asm("mov.b64 %0, {%1, %2};" : "=l"(d) : "f"(lo), "f"(hi)); return d;
}
__device__ __forceinline__ void upk2(u64 v, float& lo, float& hi) {
    asm("mov.b64 {%0, %1}, %2;" : "=f"(lo), "=f"(hi) : "l"(v));
}
__device__ __forceinline__ u64 fma2(u64 a, u64 b, u64 c) {
    u64 d; asm("fma.rn.f32x2 %0, %1, %2, %3;" : "=l"(d) : "l"(a), "l"(b), "l"(c)); return d;
}

__device__ __forceinline__ int q_of(float t) {
    // t*1024 is exact in fp32 (power-of-two scale), so truncation == floor,
    // matching the reference's interval comparisons bit-exactly.
    int q = (int)(t * 1024.0f);
    q = q < 0 ? 0 : (q > 1023 ? 1023 : q);
    return q;
}

// Fused: each block builds the 1024-entry LUT in shared memory — one QUAD of
// entries (q = 4g..4g+3) per thread, sharing levels 0..7 rows+signs, the
// level-8 row, and two level-9 rows. Then applies the LUT (1 float4/thread).
__global__ void __launch_bounds__(256) haar_fused(const float* __restrict__ t,
                                                  const float* __restrict__ W1,
                                                  const float* __restrict__ b1,
                                                  const float* __restrict__ W2,
                                                  const float* __restrict__ b2,
                                                  const float* __restrict__ W3,
                                                  const float* __restrict__ b3,
                                                  float* __restrict__ out,
                                                  int n) {
    __shared__ float4 tab[1024];
    __shared__ u64 w3s[12];   // w3s[f*4+kk] = (W3[2kk][f], W3[2kk+1][f])

    int tid = threadIdx.x;
    int i = blockIdx.x * blockDim.x + tid;
    int n4 = n >> 2;

    // ---- Prefetch this thread's input points (latency hides behind build) ----
    const float4* t4 = reinterpret_cast<const float4*>(t);
    float4 tv = make_float4(0.f, 0.f, 0.f, 0.f);
    if (i < n4) tv = t4[i];
    int tail_start = n4 << 2;
    int tail_n = n - tail_start;
    float t_tail = 0.f;
    if (i < tail_n) t_tail = t[tail_start + i];

    // ---- Stage packed W3 pairs into smem ----
    if (tid < 12) {
        int f = tid % 3, kk = tid / 3;
        w3s[f * 4 + kk] = pk2(W3[(2 * kk) * 3 + f], W3[(2 * kk + 1) * 3 + f]);
    }

    // ---- Per-thread register preloads (warp-uniform-ish, L1/L2 hits) ----
    const ulonglong2* w2v = reinterpret_cast<const ulonglong2*>(W2);
    u64 w2p[32];
#pragma unroll
    for (int r = 0; r < 16; r++) { ulonglong2 v = w2v[r]; w2p[2*r] = v.x; w2p[2*r+1] = v.y; }

    const ulonglong2* b1v = reinterpret_cast<const ulonglong2*>(b1);
    u64 b1p[4];
    { ulonglong2 v0 = b1v[0], v1 = b1v[1]; b1p[0]=v0.x; b1p[1]=v0.y; b1p[2]=v1.x; b1p[3]=v1.y; }

    const ulonglong2* b2v = reinterpret_cast<const ulonglong2*>(b2);
    u64 b2p[4];
    { ulonglong2 v0 = b2v[0], v1 = b2v[1]; b2p[0]=v0.x; b2p[1]=v0.y; b2p[2]=v1.x; b2p[3]=v1.y; }

    float b3r[3];
#pragma unroll
    for (int f = 0; f < 3; f++) b3r[f] = b3[f];

    __syncthreads();   // w3s visible

    const ulonglong2* w1v = reinterpret_cast<const ulonglong2*>(W1);

    // ---- Build: ONE quad (entries 4g..4g+3) per thread, g = tid (0..255) ----
    {
        int g = tid;

        u64 base2[4];
#pragma unroll
        for (int h = 0; h < 4; h++) base2[h] = b1p[h];

        // Levels 0..7: rows AND signs shared by the whole quad.
#pragma unroll
        for (int j = 0; j < 8; j++) {
            int k   = g >> (8 - j);
            int row = (1 << j) - 1 + k;
            float s = ((g >> (7 - j)) & 1) ? -1.0f : 1.0f;
            u64 s2 = pk2(s, s);
            ulonglong2 r0 = __ldg(w1v + row * 2);
            ulonglong2 r1 = __ldg(w1v + row * 2 + 1);
            base2[0] = fma2(s2, r0.x, base2[0]);
            base2[1] = fma2(s2, r0.y, base2[1]);
            base2[2] = fma2(s2, r1.x, base2[2]);
            base2[3] = fma2(s2, r1.y, base2[3]);
        }

        // Level-8 row (shared; sign +,+,-,- over c) and two level-9 rows.
        ulonglong2 a0 = __ldg(w1v + (255 + g) * 2);
        ulonglong2 a1 = __ldg(w1v + (255 + g) * 2 + 1);
        u64 r8[4]  = { a0.x, a0.y, a1.x, a1.y };
        ulonglong2 c0 = __ldg(w1v + (511 + 2 * g) * 2);
        ulonglong2 c1 = __ldg(w1v + (511 + 2 * g) * 2 + 1);
        u64 r9a[4] = { c0.x, c0.y, c1.x, c1.y };
        ulonglong2 d0 = __ldg(w1v + (512 + 2 * g) * 2);
        ulonglong2 d1 = __ldg(w1v + (512 + 2 * g) * 2 + 1);
        u64 r9b[4] = { d0.x, d0.y, d1.x, d1.y };

#pragma unroll
        for (int c = 0; c < 4; c++) {
            float s8 = (c & 2) ? -1.0f : 1.0f;
            float s9 = (c & 1) ? -1.0f : 1.0f;
            u64 s8p = pk2(s8, s8);
            u64 s9p = pk2(s9, s9);
            const u64* r9 = (c & 2) ? r9b : r9a;

            // acc = base + s8*r8 + s9*r9; ReLU; broadcast lanes into pairs.
            u64 bc[8];
#pragma unroll
            for (int h = 0; h < 4; h++) {
                u64 a2 = fma2(s8p, r8[h], base2[h]);
                a2 = fma2(s9p, r9[h], a2);
                float lo, hi; upk2(a2, lo, hi);
                lo = fmaxf(lo, 0.0f); hi = fmaxf(hi, 0.0f);
                bc[2*h]   = pk2(lo, lo);
                bc[2*h+1] = pk2(hi, hi);
            }

            // Layer 2: h2 pairs (k, k+1); W2 pairs in registers.
            u64 h2p[4];
#pragma unroll
            for (int kk = 0; kk < 4; kk++) h2p[kk] = b2p[kk];
#pragma unroll
            for (int h = 0; h < 8; h++) {
#pragma unroll
                for (int kk = 0; kk < 4; kk++)
                    h2p[kk] = fma2(bc[h], w2p[h * 4 + kk], h2p[kk]);
            }
#pragma unroll
            for (int kk = 0; kk < 4; kk++) {
                float lo, hi; upk2(h2p[kk], lo, hi);
                h2p[kk] = pk2(fmaxf(lo, 0.0f), fmaxf(hi, 0.0f));
            }

            // Layer 3: packed dot over k-pairs + horizontal add.
            float o[3];
#pragma unroll
            for (int f = 0; f < 3; f++) {
                u64 acc = pk2(b3r[f], 0.0f);
#pragma unroll
                for (int kk = 0; kk < 4; kk++)
                    acc = fma2(h2p[kk], w3s[f * 4 + kk], acc);
                float lo, hi; upk2(acc, lo, hi);
                o[f] = lo + hi;
            }

            tab[4 * g + c] = make_float4(o[0], o[1], o[2], 0.0f);
        }
    }

    __syncthreads();

    // ---- Apply: 4 points (one float4) per thread ----
    float4* o4 = reinterpret_cast<float4*>(out);
    if (i < n4) {
        float4 r0 = tab[q_of(tv.x)];
        float4 r1 = tab[q_of(tv.y)];
        float4 r2 = tab[q_of(tv.z)];
        float4 r3 = tab[q_of(tv.w)];

        o4[3 * i + 0] = make_float4(r0.x, r0.y, r0.z, r1.x);
        o4[3 * i + 1] = make_float4(r1.y, r1.z, r2.x, r2.y);
        o4[3 * i + 2] = make_float4(r2.z, r3.x, r3.y, r3.z);
    }

    // Scalar tail (n not divisible by 4) — dead for n = 131072 but kept correct.
    if (i < tail_n) {
        int pidx = tail_start + i;
        float4 r = tab[q_of(t_tail)];
        out[3 * pidx + 0] = r.x;
        out[3 * pidx + 1] = r.y;
        out[3 * pidx + 2] = r.z;
    }
}

extern "C" void kernel_launch(void* const* d_in, const int* in_sizes, int n_in,
                              void* d_out, int out_size) {
    const float* t  = (const float*)d_in[0];
    const float* W1 = (const float*)d_in[1];
    const float* b1 = (const float*)d_in[2];
    const float* W2 = (const float*)d_in[3];
    const float* b2 = (const float*)d_in[4];
    const float* W3 = (const float*)d_in[5];
    const float* b3 = (const float*)d_in[6];
    float* out = (float*)d_out;

    int n = in_sizes[0];  // B*T points

    int n4 = n >> 2;
    int threads = 256;
    int blocks = (n4 + threads - 1) / threads;
    if (blocks < 1) blocks = 1;
    haar_fused<<<blocks, threads>>>(t, W1, b1, W2, b2, W3, b3, out, n);
}